// round 4
// baseline (speedup 1.0000x reference)
#include <cuda_runtime.h>
#include <cuda_bf16.h>
#include <cstdint>

// ---------------- problem constants ----------------
#define BB   2
#define CC   128
#define HH   128
#define WW   128
#define HL   64
#define WL   64
#define QQ   65536
#define BQ   (BB*QQ)          // 131072
#define RTOT (4*BQ)           // 524288
#define HID  256
#define K0R  262              // real in_dim
#define K0P  272              // padded to 16*17

typedef unsigned long long ull;

// ---------------- device scratch (static; no allocation) ----------------
__device__ float g_featT[(size_t)BB*HH*WW*CC];     // NHWC feat   (16.8 MB)
__device__ float g_lrT  [(size_t)BB*HL*WL*CC];     // NHWC lr     ( 4.2 MB)
__device__ float g_predArea[(size_t)RTOT*4];       // pred.xyz + area (33.5 MB)

// ---------------- f32x2 helpers ----------------
__device__ __forceinline__ ull pack2(float x, float y) {
    ull r;
    asm("mov.b64 %0, {%1, %2};" : "=l"(r) : "f"(x), "f"(y));
    return r;
}
__device__ __forceinline__ void unpack2(ull v, float& x, float& y) {
    asm("mov.b64 {%0, %1}, %2;" : "=f"(x), "=f"(y) : "l"(v));
}
__device__ __forceinline__ void fma2(ull& d, ull a, ull b) {
    asm("fma.rn.f32x2 %0, %1, %2, %0;" : "+l"(d) : "l"(a), "l"(b));
}

// D-layout: activations stored as u64 row-pair units.
// Unit (k, u) holds (act[k][2u], act[k][2u+1]) at u64-index k*32 + (u XOR (k&31)).
// Float address of element (k, r):
__device__ __forceinline__ int daddr(int k, int r) {
    int u = r >> 1;
    return (k * 32 + (u ^ (k & 31))) * 2 + (r & 1);
}

// ---------------- kernel 1: NCHW -> NHWC tiled transpose (C = 128) ----------------
__global__ void transpose_kernel(const float* __restrict__ src, int Hh, int Ww, int mode)
{
    __shared__ float tile[32][33];
    float* dst = mode ? g_lrT : g_featT;
    const int x0 = blockIdx.x * 32;
    const int c0 = blockIdx.y * 32;
    const int bz = blockIdx.z;                 // b*Hh + y
    const int b  = bz / Hh, y = bz % Hh;
    const int txi = threadIdx.x, tyi = threadIdx.y;   // 32 x 8
#pragma unroll
    for (int j = 0; j < 4; j++) {
        int c = c0 + tyi + j * 8;
        tile[tyi + j * 8][txi] =
            src[(((size_t)b * CC + c) * Hh + y) * Ww + x0 + txi];
    }
    __syncthreads();
#pragma unroll
    for (int j = 0; j < 4; j++) {
        int x = x0 + tyi + j * 8;
        dst[(((size_t)b * Hh + y) * Ww + x) * CC + c0 + txi] = tile[txi][tyi + j * 8];
    }
}

// ---------------- fused MLP layer: 64 rows x 256 cols, D-layout activations ----------
// Thread map: tx = lane (0..31), ty = warp (0..7).
// Thread owns cols {tx+32i, i=0..7}, row-pairs u = 4ty+v (rows 8ty..8ty+7).
// Weights staged into SMEM pre-duplicated: wdup[kk][c] = (w, w) as u64.
// Inner loop: zero MOVs -- a = natural act pair (broadcast LDS.64),
//             b = duplicated weight pair (conflict-free LDS.64).
template<int KREAL, int KPAD, bool RELU>
__device__ __forceinline__ void mlp_layer(const float* __restrict__ Wg,
                                          const float* __restrict__ bg,
                                          const float* __restrict__ inBuf,
                                          float* __restrict__ outBuf,
                                          float* __restrict__ wtBuf,
                                          float* __restrict__ bias,
                                          int tx, int ty)
{
    const int t = threadIdx.x;
    const ull* inU = (const ull*)inBuf;
    ull* outU = (ull*)outBuf;
    ull* wd   = (ull*)wtBuf;

    __syncthreads();                     // previous layer fully done
    bias[t] = bg[t];
    __syncthreads();

    ull acc[8][4];
#pragma unroll
    for (int i = 0; i < 8; i++) {
        float bv = bias[tx + 32 * i];
        ull bp = pack2(bv, bv);          // 8 packs per layer -- negligible
#pragma unroll
        for (int v = 0; v < 4; v++) acc[i][v] = bp;
    }

    constexpr int NKB = KPAD / 16;
    for (int kb = 0; kb < NKB; kb++) {
        __syncthreads();                 // wdup reuse protection
#pragma unroll
        for (int i = 0; i < 16; i++) {   // stage 16x256 weights, duplicated
            int j = i * 256 + t;         // kk*256 + c
            int gidx = kb * 4096 + j;
            float w = 0.f;
            if (KREAL == KPAD || gidx < KREAL * 256) w = Wg[gidx];
            wd[j] = pack2(w, w);         // STS.64, lanes 8B apart: conflict-free
        }
        __syncthreads();
#pragma unroll
        for (int kk = 0; kk < 16; kk++) {
            const int k  = kb * 16 + kk;
            const int ks = k & 31;
            ull a[4];                    // broadcast LDS.64 (same addr warp-wide)
#pragma unroll
            for (int v = 0; v < 4; v++)
                a[v] = inU[k * 32 + ((4 * ty + v) ^ ks)];
            ull w[8];                    // conflict-free LDS.64
#pragma unroll
            for (int i = 0; i < 8; i++)
                w[i] = wd[kk * 256 + tx + 32 * i];
#pragma unroll
            for (int i = 0; i < 8; i++)
#pragma unroll
                for (int v = 0; v < 4; v++)
                    fma2(acc[i][v], a[v], w[i]);
        }
    }
    // epilogue: D-layout stores, bank 2*(u XOR tx) -> conflict-free STS.64
#pragma unroll
    for (int i = 0; i < 8; i++) {
        int c = tx + 32 * i;
#pragma unroll
        for (int v = 0; v < 4; v++) {
            float lo, hi;
            unpack2(acc[i][v], lo, hi);  // register-pair aliasing: free
            if (RELU) { lo = fmaxf(lo, 0.f); hi = fmaxf(hi, 0.f); }
            int u = 4 * ty + v;
            outU[c * 32 + (u ^ tx)] = pack2(lo, hi);
        }
    }
}

// ---------------- kernel 3: fused gather + 5-layer MLP ----------------
__global__ void __launch_bounds__(256, 1) mlp_kernel(
    const float* __restrict__ coord, const float* __restrict__ cell,
    const float* __restrict__ W0, const float* __restrict__ b0,
    const float* __restrict__ W1, const float* __restrict__ b1,
    const float* __restrict__ W2, const float* __restrict__ b2,
    const float* __restrict__ W3, const float* __restrict__ b3,
    const float* __restrict__ W4, const float* __restrict__ b4)
{
    extern __shared__ float smem[];
    float* bufA  = smem;                       // D-layout, 272 k x 32 u64 = 17408 floats
    float* bufB  = bufA + K0P * 32 * 2;        // D-layout, 256 k          = 16384 floats
    float* wtBuf = bufB + 256 * 32 * 2;        // wdup: 16x256 u64         =  8192 floats
    float* bias  = wtBuf + 16 * 256 * 2;       // [256]
    float* areaS = bias + 256;                 // [64]

    const int t    = threadIdx.x;
    const int rowL = t >> 2;
    const int sub  = t & 3;
    const long rg  = (long)blockIdx.x * 64 + rowL;
    const int s    = (int)(rg >> 17);       // / BQ
    const int rem  = (int)(rg & (BQ - 1));  // b*Q + q
    const int b    = rem >> 16;             // / Q

    // ---- phase 0: per-row geometry + feature gathers into bufA (D-layout) ----
    const float cy = coord[2 * rem + 0];
    const float cx = coord[2 * rem + 1];
    const float vx = (s & 2) ? 1.f : -1.f;
    const float vy = (s & 1) ? 1.f : -1.f;
    const float r128 = 1.f / 128.f;
    float cy_ = cy + (vx * r128 + 1e-6f);
    float cx_ = cx + (vy * r128 + 1e-6f);
    cy_ = fminf(fmaxf(cy_, -1.f + 1e-6f), 1.f - 1e-6f);
    cx_ = fminf(fmaxf(cx_, -1.f + 1e-6f), 1.f - 1e-6f);
    int iy  = (int)floorf(((cy_ + 1.f) * 128.f - 1.f) * 0.5f + 0.5f);
    int ix  = (int)floorf(((cx_ + 1.f) * 128.f - 1.f) * 0.5f + 0.5f);
    iy = min(max(iy, 0), 127); ix = min(max(ix, 0), 127);
    int liy = (int)floorf(((cy_ + 1.f) * 64.f - 1.f) * 0.5f + 0.5f);
    int lix = (int)floorf(((cx_ + 1.f) * 64.f - 1.f) * 0.5f + 0.5f);
    liy = min(max(liy, 0), 63); lix = min(max(lix, 0), 63);

    if (sub == 0) {
        float qy = -1.f + (2.f * (float)iy + 1.f) * r128;
        float qx = -1.f + (2.f * (float)ix + 1.f) * r128;
        float rel_y = (cy - qy) * 128.f;
        float rel_x = (cx - qx) * 128.f;
        bufA[daddr(128, rowL)] = rel_y;
        bufA[daddr(129, rowL)] = rel_x;
        bufA[daddr(258, rowL)] = -1.f + (2.f * (float)liy + 1.f) * (1.f / 64.f);
        bufA[daddr(259, rowL)] = -1.f + (2.f * (float)lix + 1.f) * (1.f / 64.f);
        bufA[daddr(260, rowL)] = cell[2 * rem + 0] * 128.f;
        bufA[daddr(261, rowL)] = cell[2 * rem + 1] * 128.f;
#pragma unroll
        for (int k = K0R; k < K0P; k++) bufA[daddr(k, rowL)] = 0.f;  // zero pad
        areaS[rowL] = fabsf(rel_y * rel_x) + 1e-9f;
    }
    {   // hi-res features: channels [0..127]
        const float4* fb = (const float4*)(g_featT + (size_t)(((b * HH + iy) * WW + ix)) * CC);
#pragma unroll
        for (int i = 0; i < 8; i++) {
            float4 v = fb[sub * 8 + i];
            int c = (sub * 8 + i) * 4;
            bufA[daddr(c + 0, rowL)] = v.x;
            bufA[daddr(c + 1, rowL)] = v.y;
            bufA[daddr(c + 2, rowL)] = v.z;
            bufA[daddr(c + 3, rowL)] = v.w;
        }
        // lr features: channels [130..257]
        const float4* lb = (const float4*)(g_lrT + (size_t)(((b * HL + liy) * WL + lix)) * CC);
#pragma unroll
        for (int i = 0; i < 8; i++) {
            float4 v = lb[sub * 8 + i];
            int c = 130 + (sub * 8 + i) * 4;
            bufA[daddr(c + 0, rowL)] = v.x;
            bufA[daddr(c + 1, rowL)] = v.y;
            bufA[daddr(c + 2, rowL)] = v.z;
            bufA[daddr(c + 3, rowL)] = v.w;
        }
    }

    // ---- layers 0..3 ----
    const int tx = t & 31, ty = t >> 5;
    mlp_layer<K0R, K0P, true>(W0, b0, bufA, bufB, wtBuf, bias, tx, ty);
    mlp_layer<256, 256, true>(W1, b1, bufB, bufA, wtBuf, bias, tx, ty);
    mlp_layer<256, 256, true>(W2, b2, bufA, bufB, wtBuf, bias, tx, ty);
    mlp_layer<256, 256, true>(W3, b3, bufB, bufA, wtBuf, bias, tx, ty);

    // ---- layer 4: 256 -> 3, no relu; write pred + area ----
    __syncthreads();
    if (t < 192) {
#pragma unroll
        for (int i = 0; i < 4; i++) wtBuf[t * 4 + i] = W4[t * 4 + i];   // 768 floats
    }
    if (t < 3) bias[t] = b4[t];
    __syncthreads();
    if (t < 192) {
        const int r  = t / 3;
        const int oc = t - 3 * r;
        float acc = bias[oc];
#pragma unroll 8
        for (int k = 0; k < 256; k++)
            acc = fmaf(bufA[daddr(k, r)], wtBuf[k * 3 + oc], acc);
        const size_t rgi = (size_t)((long)blockIdx.x * 64 + r) * 4;
        g_predArea[rgi + oc] = acc;
        if (oc == 0) g_predArea[rgi + 3] = areaS[r];
    }
}

// ---------------- kernel 4: local-ensemble combine (diagonal area swap) -------------
__global__ void combine_kernel(float* __restrict__ out)
{
    const int idx = blockIdx.x * 256 + threadIdx.x;     // b*Q + q
    const float4 p0 = *(const float4*)(g_predArea + ((size_t)(0 * BQ + idx)) * 4);
    const float4 p1 = *(const float4*)(g_predArea + ((size_t)(1 * BQ + idx)) * 4);
    const float4 p2 = *(const float4*)(g_predArea + ((size_t)(2 * BQ + idx)) * 4);
    const float4 p3 = *(const float4*)(g_predArea + ((size_t)(3 * BQ + idx)) * 4);
    const float tot = p0.w + p1.w + p2.w + p3.w;
    const float w0 = p3.w / tot, w1 = p2.w / tot, w2 = p1.w / tot, w3 = p0.w / tot;
    out[idx * 3 + 0] = p0.x * w0 + p1.x * w1 + p2.x * w2 + p3.x * w3;
    out[idx * 3 + 1] = p0.y * w0 + p1.y * w1 + p2.y * w2 + p3.y * w3;
    out[idx * 3 + 2] = p0.z * w0 + p1.z * w1 + p2.z * w2 + p3.z * w3;
}

// ---------------- launch ----------------
extern "C" void kernel_launch(void* const* d_in, const int* in_sizes, int n_in,
                              void* d_out, int out_size)
{
    const float* feat  = (const float*)d_in[0];
    const float* lrft  = (const float*)d_in[1];
    const float* coord = (const float*)d_in[2];
    const float* cell  = (const float*)d_in[3];
    const float* W0 = (const float*)d_in[4];   const float* b0 = (const float*)d_in[5];
    const float* W1 = (const float*)d_in[6];   const float* b1 = (const float*)d_in[7];
    const float* W2 = (const float*)d_in[8];   const float* b2 = (const float*)d_in[9];
    const float* W3 = (const float*)d_in[10];  const float* b3 = (const float*)d_in[11];
    const float* W4 = (const float*)d_in[12];  const float* b4 = (const float*)d_in[13];
    float* out = (float*)d_out;

    const size_t SMEM_FLOATS = (size_t)K0P * 32 * 2     // bufA 17408
                             + (size_t)256 * 32 * 2     // bufB 16384
                             + 16 * 256 * 2             // wdup  8192
                             + 256                      // bias
                             + 64;                      // area
    const size_t SMEM_BYTES = SMEM_FLOATS * sizeof(float);  // ~165.3 KB
    cudaFuncSetAttribute((const void*)mlp_kernel,
                         cudaFuncAttributeMaxDynamicSharedMemorySize, (int)SMEM_BYTES);

    dim3 blkT(32, 8);
    transpose_kernel<<<dim3(WW / 32, CC / 32, BB * HH), blkT>>>(feat, HH, WW, 0);
    transpose_kernel<<<dim3(WL / 32, CC / 32, BB * HL), blkT>>>(lrft, HL, WL, 1);

    mlp_kernel<<<RTOT / 64, 256, SMEM_BYTES>>>(coord, cell,
                                               W0, b0, W1, b1, W2, b2, W3, b3, W4, b4);

    combine_kernel<<<BQ / 256, 256>>>(out);
}

// round 9
// speedup vs baseline: 3.1087x; 3.1087x over previous
#include <cuda_runtime.h>
#include <cuda_bf16.h>
#include <cstdint>

// ---------------- problem constants ----------------
#define BB   2
#define CC   128
#define HH   128
#define WW   128
#define HL   64
#define WL   64
#define QQ   65536
#define BQ   (BB*QQ)          // 131072
#define RTOT (4*BQ)           // 524288
#define ROWS 128              // rows per CTA (MMA M)
#define NCTA (RTOT/ROWS)      // 4096

// ---------------- smem layout (bytes) ----------------
// A buffers: [128 r][32 segs of 8 bf16], unit = r*32 + (seg ^ (r&7)), 16B units
#define A_HI 0                // 65536
#define A_LO 65536            // 65536
// B staging: [256 n][16 segs] (k-half of 128), unit = n*16 + (seg ^ (n&7))
#define BST  131072           // 65536
#define BIAS 196608           // 256 f32
#define W4S  197632           // [3][256] f32
#define WT   200704           // wtail [6][256] f32
#define XT   206848           // xtail [6][128] f32 (reused for head partials)
#define AREA 209920           // 128 f32
#define SMEMB 210432
#define VSTR 258              // fp32 v-buffer row stride (overlays A_HI/A_LO at l==3)

// ---------------- device scratch (static; no allocation) ----------------
__device__ float g_featT[(size_t)BB*HH*WW*CC];       // NHWC feat fp32
__device__ float g_lrT  [(size_t)BB*HL*WL*CC];       // NHWC lr fp32
__device__ float g_predArea[(size_t)RTOT*4];         // pred.xyz + area
// weights pre-transposed to [layer][n 0..255][k 0..255] bf16 (hi and residual-lo)
__device__ __nv_bfloat16 g_Bh[4*65536];
__device__ __nv_bfloat16 g_Bl[4*65536];

__device__ __forceinline__ uint32_t smem_u32(const void* p) {
    uint32_t a;
    asm("{ .reg .u64 t; cvta.to.shared.u64 t, %1; cvt.u32.u64 %0, t; }" : "=r"(a) : "l"(p));
    return a;
}
__device__ __forceinline__ void ldsm4(uint32_t& q0, uint32_t& q1, uint32_t& q2, uint32_t& q3,
                                      uint32_t addr) {
    asm volatile("ldmatrix.sync.aligned.m8n8.x4.shared.b16 {%0,%1,%2,%3}, [%4];"
                 : "=r"(q0), "=r"(q1), "=r"(q2), "=r"(q3) : "r"(addr));
}
__device__ __forceinline__ void mma_bf16(float* d, const uint32_t* a, const uint32_t* b) {
    asm volatile("mma.sync.aligned.m16n8k16.row.col.f32.bf16.bf16.f32 "
                 "{%0,%1,%2,%3}, {%4,%5,%6,%7}, {%8,%9}, {%0,%1,%2,%3};"
                 : "+f"(d[0]), "+f"(d[1]), "+f"(d[2]), "+f"(d[3])
                 : "r"(a[0]), "r"(a[1]), "r"(a[2]), "r"(a[3]), "r"(b[0]), "r"(b[1]));
}
__device__ __forceinline__ uint32_t pk(__nv_bfloat16 a, __nv_bfloat16 b) {
    return (uint32_t)__bfloat16_as_ushort(a) | ((uint32_t)__bfloat16_as_ushort(b) << 16);
}

// ---------------- kernel 1: NCHW -> NHWC tiled transpose ----------------
__global__ void transpose_kernel(const float* __restrict__ src, int Hh, int Ww, int mode)
{
    __shared__ float tile[32][33];
    float* dst = mode ? g_lrT : g_featT;
    const int x0 = blockIdx.x * 32;
    const int c0 = blockIdx.y * 32;
    const int bz = blockIdx.z;
    const int b  = bz / Hh, y = bz % Hh;
    const int txi = threadIdx.x, tyi = threadIdx.y;   // 32 x 8
#pragma unroll
    for (int j = 0; j < 4; j++) {
        int c = c0 + tyi + j * 8;
        tile[tyi + j * 8][txi] = src[(((size_t)b * CC + c) * Hh + y) * Ww + x0 + txi];
    }
    __syncthreads();
#pragma unroll
    for (int j = 0; j < 4; j++) {
        int x = x0 + tyi + j * 8;
        dst[(((size_t)b * Hh + y) * Ww + x) * CC + c0 + txi] = tile[txi][tyi + j * 8];
    }
}

// ---------------- kernel 2: weight prep (transpose + bf16 split) ----------------
__global__ void prep_weights(const float* __restrict__ W0, const float* __restrict__ W1,
                             const float* __restrict__ W2, const float* __restrict__ W3)
{
    int id = blockIdx.x * 256 + threadIdx.x;      // 4*256*256
    int l  = id >> 16;
    int n  = (id >> 8) & 255;
    int k  = id & 255;
    const float* Wl = (l == 0) ? W0 : (l == 1) ? W1 : (l == 2) ? W2 : W3;
    // layer0 k remap: k<128 -> feat chan k ; k>=128 -> lr chan => W0 row 130+(k-128)
    int ksrc = (l == 0 && k >= 128) ? (130 + (k - 128)) : k;
    float w = Wl[ksrc * 256 + n];
    __nv_bfloat16 h  = __float2bfloat16(w);
    __nv_bfloat16 lo = __float2bfloat16(w - __bfloat162float(h));
    g_Bh[id] = h;
    g_Bl[id] = lo;
}

// stage one k-half (128 k) of one layer's B into SMEM, swizzled
__device__ __forceinline__ void stageB(const __nv_bfloat16* src, char* smem, int kc, int t)
{
    const uint4* s = (const uint4*)src;
#pragma unroll
    for (int i = 0; i < 16; i++) {
        int idx = i * 256 + t;                    // 0..4095
        int n = idx >> 4, sg = idx & 15;
        uint4 v = s[n * 32 + kc * 16 + sg];
        int unit = n * 16 + (sg ^ (n & 7));
        *(uint4*)(smem + BST + unit * 16) = v;
    }
}

// split fp32 pair -> bf16 hi/lo, store to A buffers (swizzled)
__device__ __forceinline__ void store_pair(char* smem, int r0, int c, float v0, float v1)
{
    __nv_bfloat16 h0 = __float2bfloat16(v0), h1 = __float2bfloat16(v1);
    __nv_bfloat16 g0 = __float2bfloat16(v0 - __bfloat162float(h0));
    __nv_bfloat16 g1 = __float2bfloat16(v1 - __bfloat162float(h1));
    int unit = r0 * 32 + ((c >> 3) ^ (r0 & 7));
    int boff = unit * 16 + (c & 7) * 2;
    *(uint32_t*)(smem + A_HI + boff) = pk(h0, h1);
    *(uint32_t*)(smem + A_LO + boff) = pk(g0, g1);
}

// ---------------- kernel 3: fused gather + HMMA MLP ----------------
__global__ void __launch_bounds__(256, 1) mlp_mma(
    const float* __restrict__ coord, const float* __restrict__ cell,
    const float* __restrict__ W0, const float* __restrict__ b0,
    const float* __restrict__ b1, const float* __restrict__ b2,
    const float* __restrict__ b3,
    const float* __restrict__ W4, const float* __restrict__ b4)
{
    extern __shared__ char smem[];
    float* smf = (float*)smem;
    const int t = threadIdx.x;
    const int lane = t & 31, w = t >> 5;
    const uint32_t sb = smem_u32(smem);

    // ---- phase 0: geometry + gathers (2 threads per row) ----
    {
        const int r = t >> 1, half = t & 1;
        const int rg  = blockIdx.x * ROWS + r;
        const int s   = rg >> 17;
        const int rem = rg & (BQ - 1);
        const int b   = rem >> 16;
        const float cy = coord[2 * rem + 0];
        const float cx = coord[2 * rem + 1];
        const float vx = (s & 2) ? 1.f : -1.f;
        const float vy = (s & 1) ? 1.f : -1.f;
        const float r128 = 1.f / 128.f;
        float cy_ = fminf(fmaxf(cy + (vx * r128 + 1e-6f), -1.f + 1e-6f), 1.f - 1e-6f);
        float cx_ = fminf(fmaxf(cx + (vy * r128 + 1e-6f), -1.f + 1e-6f), 1.f - 1e-6f);
        int iy  = min(max((int)floorf(((cy_ + 1.f) * 128.f - 1.f) * 0.5f + 0.5f), 0), 127);
        int ix  = min(max((int)floorf(((cx_ + 1.f) * 128.f - 1.f) * 0.5f + 0.5f), 0), 127);
        int liy = min(max((int)floorf(((cy_ + 1.f) * 64.f - 1.f) * 0.5f + 0.5f), 0), 63);
        int lix = min(max((int)floorf(((cx_ + 1.f) * 64.f - 1.f) * 0.5f + 0.5f), 0), 63);
        if (half == 0) {
            float qy = -1.f + (2.f * (float)iy + 1.f) * r128;
            float qx = -1.f + (2.f * (float)ix + 1.f) * r128;
            float rel_y = (cy - qy) * 128.f;
            float rel_x = (cx - qx) * 128.f;
            smf[XT / 4 + 0 * 128 + r] = rel_y;
            smf[XT / 4 + 1 * 128 + r] = rel_x;
            smf[XT / 4 + 2 * 128 + r] = -1.f + (2.f * (float)liy + 1.f) * (1.f / 64.f);
            smf[XT / 4 + 3 * 128 + r] = -1.f + (2.f * (float)lix + 1.f) * (1.f / 64.f);
            smf[XT / 4 + 4 * 128 + r] = cell[2 * rem + 0] * 128.f;
            smf[XT / 4 + 5 * 128 + r] = cell[2 * rem + 1] * 128.f;
            smf[AREA / 4 + r] = fabsf(rel_y * rel_x) + 1e-9f;
        }
        const float4* fb = half
            ? (const float4*)(g_lrT   + (size_t)(((b * HL + liy) * WL + lix)) * CC)
            : (const float4*)(g_featT + (size_t)(((b * HH + iy) * WW + ix)) * CC);
        const int r7r = r & 7;
#pragma unroll 8
        for (int i = 0; i < 32; i++) {
            float4 u = fb[i];
            int c = half * 128 + i * 4;
            __nv_bfloat16 h0 = __float2bfloat16(u.x), h1 = __float2bfloat16(u.y);
            __nv_bfloat16 h2 = __float2bfloat16(u.z), h3 = __float2bfloat16(u.w);
            __nv_bfloat16 l0 = __float2bfloat16(u.x - __bfloat162float(h0));
            __nv_bfloat16 l1 = __float2bfloat16(u.y - __bfloat162float(h1));
            __nv_bfloat16 l2 = __float2bfloat16(u.z - __bfloat162float(h2));
            __nv_bfloat16 l3 = __float2bfloat16(u.w - __bfloat162float(h3));
            int unit = r * 32 + ((c >> 3) ^ r7r);
            int boff = unit * 16 + (c & 7) * 2;
            *(uint2*)(smem + A_HI + boff) = make_uint2(pk(h0, h1), pk(h2, h3));
            *(uint2*)(smem + A_LO + boff) = make_uint2(pk(l0, l1), pk(l2, l3));
        }
        // wtail: W0 rows {128,129,258,259,260,261}
        {
            const int tailrow[6] = {128, 129, 258, 259, 260, 261};
            for (int idx = t; idx < 1536; idx += 256) {
                int jj = idx >> 8, c = idx & 255;
                smf[WT / 4 + jj * 256 + c] = W0[tailrow[jj] * 256 + c];
            }
            for (int idx = t; idx < 768; idx += 256)
                smf[W4S / 4 + idx] = W4[(idx & 255) * 3 + (idx >> 8)];
        }
    }

    // ---- ldmatrix lane geometry ----
    const int laneAr = lane & 15, sa = lane >> 4, la7 = lane & 7;
    const int nb0 = w * 32 + ((lane >> 4) << 3) + (lane & 7);   // j0=0 base n
    const int sbB = (lane >> 3) & 1;
    const int rq = lane >> 2, cq = (lane & 3) * 2;

    float acc[8][16];

    for (int l = 0; l < 4; l++) {
        __syncthreads();
        {
            const float* bg = (l == 0) ? b0 : (l == 1) ? b1 : (l == 2) ? b2 : b3;
            smf[BIAS / 4 + t] = bg[t];
        }
#pragma unroll
        for (int mt = 0; mt < 8; mt++)
#pragma unroll
            for (int q = 0; q < 16; q++) acc[mt][q] = 0.f;

        for (int kc = 0; kc < 2; kc++) {
            for (int pass = 0; pass < 3; pass++) {
                if (pass != 1) {
                    __syncthreads();
                    const __nv_bfloat16* src = ((pass == 0) ? g_Bh : g_Bl) + ((size_t)l << 16);
                    stageB(src, smem, kc, t);
                    __syncthreads();
                }
                const uint32_t Ab = sb + ((pass == 1) ? A_LO : A_HI);
#pragma unroll
                for (int ks = 0; ks < 8; ks++) {
                    uint32_t bq[4][2];
                    {
                        int seg = ks * 2 + sbB;
                        int n0 = nb0, n1 = nb0 + 16;
                        uint32_t ad0 = sb + BST + (uint32_t)((n0 * 16 + (seg ^ (n0 & 7))) * 16);
                        uint32_t ad1 = sb + BST + (uint32_t)((n1 * 16 + (seg ^ (n1 & 7))) * 16);
                        ldsm4(bq[0][0], bq[0][1], bq[1][0], bq[1][1], ad0);
                        ldsm4(bq[2][0], bq[2][1], bq[3][0], bq[3][1], ad1);
                    }
                    int segA = (kc * 16 + ks * 2 + sa) ^ la7;
#pragma unroll
                    for (int mt = 0; mt < 8; mt++) {
                        int rowA = mt * 16 + laneAr;
                        uint32_t aad = Ab + (uint32_t)((rowA * 32 + segA) * 16);
                        uint32_t aq[4];
                        ldsm4(aq[0], aq[1], aq[2], aq[3], aad);
#pragma unroll
                        for (int j = 0; j < 4; j++) mma_bf16(acc[mt] + 4 * j, aq, bq[j]);
                    }
                }
            }
        }
        __syncthreads();     // all MMA done; safe to overwrite A / v-buffer

        // ---- epilogue ----
        float wtc[6][8];
        if (l == 0) {
#pragma unroll
            for (int jj = 0; jj < 6; jj++)
#pragma unroll
                for (int j = 0; j < 4; j++) {
                    int c = w * 32 + j * 8 + cq;
                    wtc[jj][2 * j]     = smf[WT / 4 + jj * 256 + c];
                    wtc[jj][2 * j + 1] = smf[WT / 4 + jj * 256 + c + 1];
                }
        }
#pragma unroll
        for (int mt = 0; mt < 8; mt++) {
            int r0 = mt * 16 + rq;
            float xtr[6], xtr8[6];
            if (l == 0) {
#pragma unroll
                for (int jj = 0; jj < 6; jj++) {
                    xtr[jj]  = smf[XT / 4 + jj * 128 + r0];
                    xtr8[jj] = smf[XT / 4 + jj * 128 + r0 + 8];
                }
            }
#pragma unroll
            for (int j = 0; j < 4; j++) {
                int c = w * 32 + j * 8 + cq;
                float bs0 = smf[BIAS / 4 + c], bs1 = smf[BIAS / 4 + c + 1];
                float v0 = acc[mt][4 * j + 0] + bs0;
                float v1 = acc[mt][4 * j + 1] + bs1;
                float v2 = acc[mt][4 * j + 2] + bs0;
                float v3 = acc[mt][4 * j + 3] + bs1;
                if (l == 0) {
#pragma unroll
                    for (int jj = 0; jj < 6; jj++) {
                        v0 = fmaf(xtr[jj],  wtc[jj][2 * j],     v0);
                        v1 = fmaf(xtr[jj],  wtc[jj][2 * j + 1], v1);
                        v2 = fmaf(xtr8[jj], wtc[jj][2 * j],     v2);
                        v3 = fmaf(xtr8[jj], wtc[jj][2 * j + 1], v3);
                    }
                }
                v0 = fmaxf(v0, 0.f); v1 = fmaxf(v1, 0.f);
                v2 = fmaxf(v2, 0.f); v3 = fmaxf(v3, 0.f);
                if (l < 3) {
                    store_pair(smem, r0,     c, v0, v1);
                    store_pair(smem, r0 + 8, c, v2, v3);
                } else {
                    *(float2*)(smf + r0 * VSTR + c)       = make_float2(v0, v1);
                    *(float2*)(smf + (r0 + 8) * VSTR + c) = make_float2(v2, v3);
                }
            }
        }
    }

    // ---- head: out = v @ W4 + b4 ----
    __syncthreads();
    {
        const int hr = t >> 1, hh = t & 1;
        float a0 = 0.f, a1 = 0.f, a2 = 0.f;
        const float* vrow = smf + hr * VSTR + hh * 128;
        const float* w4p  = smf + W4S / 4 + hh * 128;
#pragma unroll 8
        for (int c2 = 0; c2 < 128; c2++) {
            float x = vrow[c2];
            a0 = fmaf(x, w4p[0 * 256 + c2], a0);
            a1 = fmaf(x, w4p[1 * 256 + c2], a1);
            a2 = fmaf(x, w4p[2 * 256 + c2], a2);
        }
        __syncthreads();          // v-buffer reads done before XT overwrite
        smf[XT / 4 + t * 3 + 0] = a0;
        smf[XT / 4 + t * 3 + 1] = a1;
        smf[XT / 4 + t * 3 + 2] = a2;
    }
    __syncthreads();
    if (t < 128) {
        const size_t rgi = (size_t)(blockIdx.x * ROWS + t) * 4;
        g_predArea[rgi + 0] = smf[XT / 4 + (2 * t) * 3 + 0] + smf[XT / 4 + (2 * t + 1) * 3 + 0] + b4[0];
        g_predArea[rgi + 1] = smf[XT / 4 + (2 * t) * 3 + 1] + smf[XT / 4 + (2 * t + 1) * 3 + 1] + b4[1];
        g_predArea[rgi + 2] = smf[XT / 4 + (2 * t) * 3 + 2] + smf[XT / 4 + (2 * t + 1) * 3 + 2] + b4[2];
        g_predArea[rgi + 3] = smf[AREA / 4 + t];
    }
}

// ---------------- kernel 4: local-ensemble combine (diagonal area swap) -------------
__global__ void combine_kernel(float* __restrict__ out)
{
    const int idx = blockIdx.x * 256 + threadIdx.x;     // b*Q + q
    const float4 p0 = *(const float4*)(g_predArea + ((size_t)(0 * BQ + idx)) * 4);
    const float4 p1 = *(const float4*)(g_predArea + ((size_t)(1 * BQ + idx)) * 4);
    const float4 p2 = *(const float4*)(g_predArea + ((size_t)(2 * BQ + idx)) * 4);
    const float4 p3 = *(const float4*)(g_predArea + ((size_t)(3 * BQ + idx)) * 4);
    const float tot = p0.w + p1.w + p2.w + p3.w;
    const float w0 = p3.w / tot, w1 = p2.w / tot, w2 = p1.w / tot, w3 = p0.w / tot;
    out[idx * 3 + 0] = p0.x * w0 + p1.x * w1 + p2.x * w2 + p3.x * w3;
    out[idx * 3 + 1] = p0.y * w0 + p1.y * w1 + p2.y * w2 + p3.y * w3;
    out[idx * 3 + 2] = p0.z * w0 + p1.z * w1 + p2.z * w2 + p3.z * w3;
}

// ---------------- launch ----------------
extern "C" void kernel_launch(void* const* d_in, const int* in_sizes, int n_in,
                              void* d_out, int out_size)
{
    const float* feat  = (const float*)d_in[0];
    const float* lrft  = (const float*)d_in[1];
    const float* coord = (const float*)d_in[2];
    const float* cell  = (const float*)d_in[3];
    const float* W0 = (const float*)d_in[4];   const float* b0 = (const float*)d_in[5];
    const float* W1 = (const float*)d_in[6];   const float* b1 = (const float*)d_in[7];
    const float* W2 = (const float*)d_in[8];   const float* b2 = (const float*)d_in[9];
    const float* W3 = (const float*)d_in[10];  const float* b3 = (const float*)d_in[11];
    const float* W4 = (const float*)d_in[12];  const float* b4 = (const float*)d_in[13];
    float* out = (float*)d_out;

    cudaFuncSetAttribute((const void*)mlp_mma,
                         cudaFuncAttributeMaxDynamicSharedMemorySize, SMEMB);

    dim3 blkT(32, 8);
    transpose_kernel<<<dim3(WW / 32, CC / 32, BB * HH), blkT>>>(feat, HH, WW, 0);
    transpose_kernel<<<dim3(WL / 32, CC / 32, BB * HL), blkT>>>(lrft, HL, WL, 1);
    prep_weights<<<1024, 256>>>(W0, W1, W2, W3);

    mlp_mma<<<NCTA, 256, SMEMB>>>(coord, cell, W0, b0, b1, b2, b3, W4, b4);

    combine_kernel<<<BQ / 256, 256>>>(out);
}